// round 12
// baseline (speedup 1.0000x reference)
#include <cuda_runtime.h>
#include <math.h>

// ---------------- static problem config ----------------
#define B_   8
#define Q_   20
#define P_   12
#define N_   4096
#define G_   2048
#define FAC_ 64
#define M_   1280
#define KNN_ 7
#define REP_EPS 1e-12f
#define BW2 0.0009f
#define RADIUS_ 0.07f

#define BM (B_*M_)           // 10240
#define BG (B_*G_)           // 16384

#define COST_BLOCKS (B_*Q_)              // 160
#define KA_BLOCKS (COST_BLOCKS + 1)      // 161 (cost + solver)

#define CH1_BLOCKS (B_*(M_/64))          // 160
#define CH2_BLOCKS (B_*(G_/64))          // 256
#define REP_BLOCKS (B_*Q_/4)             // 40
#define KB_BLOCKS (CH1_BLOCKS + CH2_BLOCKS + REP_BLOCKS)   // 456

// ---------------- device scratch (zero-init identity; consumers restore zeros) ----------------
__device__ float g_cham [B_][Q_][P_];
__device__ float g_nsim [B_][Q_][P_];
__device__ float g_ddiff[B_][Q_][P_];
__device__ float g_costT[B_][P_][Q_];   // rows = gt planes, cols = queries
__device__ float g_cnt  [B_][P_];
__device__ float g_accs[8];             // 0=rep 1=mL1 2=mL2 3=gL1 4=gL2
__device__ float g_scalars[3];          // cls_sum, par_sum, pvd_sum (written by kA solver)
__device__ int   g_cost_done[B_];       // per-batch cost completion counters
__device__ int   g_geom_done;           // geometry ticket counter

// order-preserving float->uint key (handles negatives)
__device__ __forceinline__ unsigned fkey(float f) {
    unsigned b = __float_as_uint(f);
    return b ^ ((b >> 31) ? 0xFFFFFFFFu : 0x80000000u);
}

// ---------------- masked accumulation helper ----------------
template<int MODE>
__device__ __forceinline__ void accum_masked(const void* __restrict__ mask, long mbase,
    const float* __restrict__ pb, float nx, float ny, float nz, float dq,
    int tid, float* acc, float* cnt)
{
    for (int n = tid; n < N_; n += 256) {
        float px = pb[n*3+0], py = pb[n*3+1], pz = pb[n*3+2];
        float pp = fabsf(px*nx + py*ny + pz*nz - dq);
        #pragma unroll
        for (int p = 0; p < P_; p++) {
            long idx = mbase + (long)p * N_ + n;
            bool m;
            if (MODE == 0)      m = ((const unsigned char*)mask)[idx] != 0;
            else if (MODE == 1) m = ((const float*)mask)[idx] != 0.f;
            else                m = ((const int*)mask)[idx] != 0;
            acc[p] += m ? pp : 0.f;
            cnt[p] += m ? 1.f : 0.f;
        }
    }
}

// ================= kernel A: cost blocks + JV solver block =================
__global__ void __launch_bounds__(256) kA(const float* __restrict__ points,
                       const float* __restrict__ pn, const float* __restrict__ pd,
                       const float* __restrict__ gn, const float* __restrict__ gd,
                       const void* __restrict__ mask,
                       const float* __restrict__ logits)
{
    int bid = blockIdx.x;
    int t = threadIdx.x;

    if (bid < COST_BLOCKS) {
        // ------- cost matrix (b, q) -------
        int b = bid / Q_, q = bid % Q_;

        // mask dtype detection: block-parallel scan of first 8KB
        const unsigned char* mraw = (const unsigned char*)mask;
        bool big = false, odd = false;
        #pragma unroll 4
        for (int i = t*32; i < t*32 + 32; i++) {
            unsigned char vch = mraw[i];
            big |= (vch > 1);
            odd |= (vch == 1) && ((i & 3) != 0);
        }
        int anyBig = __syncthreads_or(big ? 1 : 0);
        int anyOdd = __syncthreads_or(odd ? 1 : 0);
        int mode = anyBig ? 1 : (anyOdd ? 0 : 2);

        float nx = pn[(b*Q_ + q)*3 + 0];
        float ny = pn[(b*Q_ + q)*3 + 1];
        float nz = pn[(b*Q_ + q)*3 + 2];
        float dq = pd[b*Q_ + q];

        __shared__ float s_acc[P_], s_cnt[P_];
        if (t < P_) { s_acc[t] = 0.f; s_cnt[t] = 0.f; }
        __syncthreads();

        float acc[P_], cnt[P_];
        #pragma unroll
        for (int p = 0; p < P_; p++) { acc[p] = 0.f; cnt[p] = 0.f; }

        const float* pb = points + (size_t)b * N_ * 3;
        const long mbase = (long)b * P_ * N_;
        if (mode == 1)      accum_masked<1>(mask, mbase, pb, nx, ny, nz, dq, t, acc, cnt);
        else if (mode == 0) accum_masked<0>(mask, mbase, pb, nx, ny, nz, dq, t, acc, cnt);
        else                accum_masked<2>(mask, mbase, pb, nx, ny, nz, dq, t, acc, cnt);

        #pragma unroll
        for (int p = 0; p < P_; p++) {
            float v = acc[p], c = cnt[p];
            #pragma unroll
            for (int off = 16; off; off >>= 1) {
                v += __shfl_down_sync(0xffffffffu, v, off);
                c += __shfl_down_sync(0xffffffffu, c, off);
            }
            if ((t & 31) == 0) { atomicAdd(&s_acc[p], v); atomicAdd(&s_cnt[p], c); }
        }
        __syncthreads();

        if (t < P_) {
            int p = t;
            float c = s_cnt[p];
            float cham = s_acc[p] / fmaxf(c, 1.f);
            float ns = 1.f - fabsf(nx*gn[(b*P_+p)*3+0] + ny*gn[(b*P_+p)*3+1] + nz*gn[(b*P_+p)*3+2]);
            float dd = fabsf(dq - gd[b*P_ + p]);
            int has = c > 0.f;
            g_cham [b][q][p] = cham;
            g_nsim [b][q][p] = ns;
            g_ddiff[b][q][p] = dd;
            g_costT[b][p][q] = ns + 0.5f*dd + 5.f*(has ? cham : 1.f);
            if (q == 0) g_cnt[b][p] = c;
        }
        __syncthreads();
        if (t == 0) { __threadfence(); atomicAdd(&g_cost_done[b], 1); }
    } else {
        // ------- solver block: per-batch-overlapped JV + cls/param/pvd -------
        __shared__ float cost_s[B_][P_*Q_];
        __shared__ float u_s[B_][P_ + 1];
        __shared__ int   s_rows[B_][P_];
        __shared__ float red[3][256];
        int w = t >> 5;        // warp = batch
        int lane = t & 31;
        const unsigned FULL = 0xffffffffu;

        // wait for this batch's 20 cost blocks
        if (lane == 0) {
            while (atomicAdd(&g_cost_done[w], 0) < Q_) __nanosleep(32);
        }
        __syncwarp();
        __threadfence();

        for (int idx = lane; idx < P_*Q_; idx += 32)
            cost_s[w][idx] = (&g_costT[w][0][0])[idx];
        if (lane == 0) u_s[w][0] = 0.f;
        __syncwarp();

        // ---- greedy row-reduction init ----
        float v = 0.f;
        int p = 0;                                      // lane j: row assigned to col j
        unsigned free_mask = ((1u << Q_) - 1u) << 1;    // cols 1..Q_ free
        unsigned todo = 0;
        for (int i = 1; i <= P_; i++) {
            float c = (lane >= 1 && lane <= Q_) ? cost_s[w][(i-1)*Q_ + (lane-1)] : 1e30f;
            unsigned key = (lane >= 1 && lane <= Q_) ? ((fkey(c) & ~31u) | (unsigned)lane)
                                                     : 0xFFFFFFFFu;
            key = __reduce_min_sync(FULL, key);
            int jm = (int)(key & 31u);
            float ui = __shfl_sync(FULL, c, jm);
            if (lane == 0) u_s[w][i] = ui;
            if ((free_mask >> jm) & 1u) {
                if (lane == jm) p = i;
                free_mask &= ~(1u << jm);
            } else {
                todo |= (1u << i);
            }
        }
        __syncwarp();

        // ---- augment remaining rows ----
        float minv = 0.f;
        int way = 0, used = 0;
        for (int i = 1; i <= P_; i++) {
            if (!((todo >> i) & 1u)) continue;
            if (lane == 0) p = i;
            minv = 1e30f; used = 0;
            int j0 = 0;
            while (true) {
                if (lane == j0) used = 1;
                int i0 = __shfl_sync(FULL, p, j0);
                float u0 = u_s[w][i0];
                bool active = (lane >= 1) && (lane <= Q_) && !used;
                if (active) {
                    float cur = cost_s[w][(i0-1)*Q_ + (lane-1)] - u0 - v;
                    if (cur < minv) { minv = cur; way = j0; }
                }
                unsigned key = active ? ((fkey(minv) & ~31u) | (unsigned)lane)
                                      : 0xFFFFFFFFu;
                key = __reduce_min_sync(FULL, key);
                int j1 = (int)(key & 31u);
                float delta = __shfl_sync(FULL, minv, j1);
                if (lane <= Q_) {
                    if (used)           { u_s[w][p] += delta; v -= delta; }
                    else if (lane >= 1) { minv -= delta; }
                }
                __syncwarp();
                j0 = j1;
                if ((free_mask >> j0) & 1u) break;
            }
            free_mask &= ~(1u << j0);
            while (j0 != 0) {
                int wy = __shfl_sync(FULL, way, j0);
                int pw = __shfl_sync(FULL, p, wy);
                if (lane == j0) p = pw;
                j0 = wy;
            }
        }
        if (lane >= 1 && lane <= Q_ && p >= 1)
            s_rows[w][p - 1] = lane - 1;
        __syncthreads();

        // ---- cls / param / pvd ----
        float c_cls = 0.f, c_par = 0.f, c_pvd = 0.f;
        if (t < B_*Q_) {
            int b = t / Q_, q = t % Q_;
            float tgt = 0.f;
            #pragma unroll
            for (int pp = 0; pp < P_; pp++) tgt += (s_rows[b][pp] == q) ? 1.f : 0.f;
            float x = logits[t];
            c_cls = fmaxf(x, 0.f) - x*tgt + log1pf(expf(-fabsf(x)));
        }
        if (t < B_*P_) {
            int b = t / P_, pp = t % P_;
            int r = s_rows[b][pp];
            c_par = g_nsim[b][r][pp] + g_ddiff[b][r][pp];
            c_pvd = (g_cnt[b][pp] > 0.f) ? g_cham[b][r][pp] : 0.f;
        }
        red[0][t] = c_cls; red[1][t] = c_par; red[2][t] = c_pvd;
        __syncthreads();
        for (int off = 128; off; off >>= 1) {
            if (t < off) {
                red[0][t] += red[0][t+off]; red[1][t] += red[1][t+off]; red[2][t] += red[2][t+off];
            }
            __syncthreads();
        }
        if (t == 0) {
            g_scalars[0] = red[0][0];
            g_scalars[1] = red[1][0];
            g_scalars[2] = red[2][0];
        }
        // restore counters for next graph replay (solver is sole consumer)
        if (t < B_) g_cost_done[t] = 0;
    }
}

// ---------------- chamfer block helper: 64 src points, float4 targets ----------------
__device__ __forceinline__ void chamfer_block(
    const float* __restrict__ srcBase, const float* __restrict__ tgtBase,
    int nTgt, int accL1, int accL2)
{
    int t = threadIdx.x;
    int pi = t & 63, s = t >> 6;
    float px = srcBase[pi*3+0], py = srcBase[pi*3+1], pz = srcBase[pi*3+2];
    float m1 = 1e30f, m2 = 1e30f;
    __shared__ float4 t4[256];
    for (int base = 0; base < nTgt; base += 256) {
        t4[t] = make_float4(tgtBase[(base+t)*3+0], tgtBase[(base+t)*3+1],
                            tgtBase[(base+t)*3+2], 0.f);
        __syncthreads();
        int j0 = s * 64;
        #pragma unroll 8
        for (int j = j0; j < j0 + 64; j++) {
            float4 w = t4[j];
            float dx = px-w.x, dy = py-w.y, dz = pz-w.z;
            float l1 = fabsf(dx) + fabsf(dy) + fabsf(dz);
            float l2 = fmaf(dx, dx, fmaf(dy, dy, dz*dz));
            m1 = fminf(m1, l1); m2 = fminf(m2, l2);
        }
        __syncthreads();
    }
    __shared__ float r1[256], r2[256];
    r1[t] = m1; r2[t] = m2;
    __syncthreads();
    if (t < 64) {
        float a1 = fminf(fminf(r1[t], r1[t+64]), fminf(r1[t+128], r1[t+192]));
        float a2 = fminf(fminf(r2[t], r2[t+64]), fminf(r2[t+128], r2[t+192]));
        #pragma unroll
        for (int off = 16; off; off >>= 1) {
            a1 += __shfl_down_sync(0xffffffffu, a1, off);
            a2 += __shfl_down_sync(0xffffffffu, a2, off);
        }
        if ((t & 31) == 0) { r1[t] = a1; r2[t] = a2; }
    }
    __syncthreads();
    if (t == 0) {
        atomicAdd(&g_accs[accL1], r1[0] + r1[32]);
        atomicAdd(&g_accs[accL2], r2[0] + r2[32]);
    }
}

// ================= kernel B: geometry + last-block final combine =================
__global__ void __launch_bounds__(256) kB(const float* __restrict__ rec,
                                          const float* __restrict__ gt,
                                          float* __restrict__ out)
{
    int bid = blockIdx.x;
    int t = threadIdx.x;

    if (bid < CH1_BLOCKS) {
        int b  = bid / (M_/64);
        int mc = bid % (M_/64);
        chamfer_block(rec + ((size_t)b*M_ + mc*64)*3, gt + (size_t)b*G_*3, G_, 1, 2);
    } else if (bid < CH1_BLOCKS + CH2_BLOCKS) {
        int id = bid - CH1_BLOCKS;
        int b  = id / (G_/64);
        int gc = id % (G_/64);
        chamfer_block(gt + ((size_t)b*G_ + gc*64)*3, rec + (size_t)b*M_*3, M_, 3, 4);
    } else {
        // repulsion: 4 (b,q) groups per block, single-writer accumulate
        int id = bid - CH1_BLOCKS - CH2_BLOCKS;   // 0..39
        int sub = t >> 6;
        int i = t & 63;
        int gq = id*4 + sub;
        int b = gq / Q_, q = gq % Q_;
        __shared__ float sx[4][FAC_], sy[4][FAC_], sz[4][FAC_];
        const float* base = rec + ((size_t)b*M_ + q*FAC_)*3;
        sx[sub][i] = base[i*3+0]; sy[sub][i] = base[i*3+1]; sz[sub][i] = base[i*3+2];
        __syncthreads();
        float px = sx[sub][i], py = sy[sub][i], pz = sz[sub][i];
        float best[KNN_];
        #pragma unroll
        for (int k = 0; k < KNN_; k++) best[k] = 1e30f;
        for (int j = 0; j < FAC_; j++) {
            if (j == i) continue;
            float dx = px-sx[sub][j], dy = py-sy[sub][j], dz = pz-sz[sub][j];
            float vv = fmaf(dx, dx, fmaf(dy, dy, dz*dz));
            #pragma unroll
            for (int k = 0; k < KNN_; k++) {
                float lo = fminf(best[k], vv);
                vv = fmaxf(best[k], vv);
                best[k] = lo;
            }
        }
        float s = 0.f;
        #pragma unroll
        for (int k = 0; k < KNN_; k++) {
            float dn = fmaxf(best[k], REP_EPS);
            s += (RADIUS_ - sqrtf(dn)) * expf(-dn / BW2);
        }
        #pragma unroll
        for (int off = 16; off; off >>= 1) s += __shfl_down_sync(0xffffffffu, s, off);
        __shared__ float sw[8];
        if ((t & 31) == 0) sw[t >> 5] = s;
        __syncthreads();
        if (t == 0) {
            float tot = 0.f;
            #pragma unroll
            for (int sb = 0; sb < 4; sb++)
                tot += fmaxf((sw[sb*2] + sw[sb*2+1]) / (float)(FAC_*KNN_), 0.f);
            atomicAdd(&g_accs[0], tot);
        }
    }

    // ---- last-arriving block performs the final combine ----
    __syncthreads();
    if (t == 0) {
        __threadfence();
        int ticket = atomicAdd(&g_geom_done, 1);
        if (ticket == KB_BLOCKS - 1) {
            __threadfence();
            float ch1 = 0.5f * (g_accs[1] / (float)BM + g_accs[3] / (float)BG);
            float ch2 = 0.5f * (g_accs[2] / (float)BM + g_accs[4] / (float)BG);
            out[0] = g_scalars[0] / (float)(B_*Q_)
                   + 0.5f  * g_scalars[1] / (float)(B_*P_)
                   + 20.f  * g_scalars[2] / (float)(B_*P_)
                   + g_accs[0] / (float)(B_*Q_)
                   + ch1 + ch2;
            // restore state for next graph replay
            #pragma unroll
            for (int k = 0; k < 8; k++) g_accs[k] = 0.f;
            g_geom_done = 0;
        }
    }
}

// ---------------- host launcher ----------------
extern "C" void kernel_launch(void* const* d_in, const int* in_sizes, int n_in,
                              void* d_out, int out_size) {
    const float* pred_logits = nullptr;
    const float* pred_normals = nullptr;
    const float* pred_distances = nullptr;
    const float* gt_normals = nullptr;
    const float* gt_distances = nullptr;
    const void*  gt_masks = nullptr;
    const float* points = nullptr;
    const float* rec = nullptr;
    const float* gt = nullptr;
    int seen160 = 0;
    for (int i = 0; i < n_in; i++) {
        switch (in_sizes[i]) {
            case B_ * Q_:
                if (seen160++ == 0) pred_logits = (const float*)d_in[i];
                else pred_distances = (const float*)d_in[i];
                break;
            case B_ * Q_ * 3: pred_normals = (const float*)d_in[i]; break;
            case B_ * P_ * 3: gt_normals = (const float*)d_in[i]; break;
            case B_ * P_: gt_distances = (const float*)d_in[i]; break;
            case B_ * P_ * N_: gt_masks = d_in[i]; break;
            case B_ * N_ * 3: points = (const float*)d_in[i]; break;
            case B_ * M_ * 3: rec = (const float*)d_in[i]; break;
            case B_ * G_ * 3: gt = (const float*)d_in[i]; break;
            default: break;  // gt_index unused
        }
    }

    kA<<<KA_BLOCKS, 256>>>(points, pred_normals, pred_distances,
                           gt_normals, gt_distances, gt_masks, pred_logits);
    kB<<<KB_BLOCKS, 256>>>(rec, gt, (float*)d_out);
}

// round 17
// speedup vs baseline: 2.3890x; 2.3890x over previous
#include <cuda_runtime.h>
#include <math.h>

// ---------------- static problem config ----------------
#define B_   8
#define Q_   20
#define P_   12
#define N_   4096
#define G_   2048
#define FAC_ 64
#define M_   1280
#define KNN_ 7
#define REP_EPS 1e-12f
#define BW2 0.0009f
#define RADIUS_ 0.07f

#define BM (B_*M_)           // 10240
#define BG (B_*G_)           // 16384

#define COST_BLOCKS (B_*Q_)              // 160
#define CH1_BLOCKS (B_*(M_/64))          // 160
#define CH2_BLOCKS (B_*(G_/64))          // 256
#define REP_BLOCKS (B_*Q_/4)             // 40
#define K1_BLOCKS (COST_BLOCKS + CH1_BLOCKS + CH2_BLOCKS + REP_BLOCKS)  // 616

// ---------------- device scratch (zero is identity; k2 restores zeros) ----------------
__device__ float g_cham [B_][Q_][P_];
__device__ float g_nsim [B_][Q_][P_];
__device__ float g_ddiff[B_][Q_][P_];
__device__ float g_costT[B_][P_][Q_];   // rows = gt planes, cols = queries
__device__ float g_cnt  [B_][P_];
__device__ int   g_rows [B_][P_];
__device__ float g_accs[8];             // 0=rep 1=mL1 2=mL2 3=gL1 4=gL2

// ---------------- packed f32x2 helpers (Blackwell) ----------------
typedef unsigned long long ull;
__device__ __forceinline__ ull pack2(float lo, float hi) {
    ull r; asm("mov.b64 %0, {%1, %2};" : "=l"(r) : "f"(lo), "f"(hi)); return r;
}
__device__ __forceinline__ void unpack2(ull v, float& lo, float& hi) {
    asm("mov.b64 {%0, %1}, %2;" : "=f"(lo), "=f"(hi) : "l"(v));
}
__device__ __forceinline__ ull addx2(ull a, ull b) {
    ull r; asm("add.rn.f32x2 %0, %1, %2;" : "=l"(r) : "l"(a), "l"(b)); return r;
}
__device__ __forceinline__ ull mulx2(ull a, ull b) {
    ull r; asm("mul.rn.f32x2 %0, %1, %2;" : "=l"(r) : "l"(a), "l"(b)); return r;
}
__device__ __forceinline__ ull fmax2(ull a, ull b, ull c) {
    ull r; asm("fma.rn.f32x2 %0, %1, %2, %3;" : "=l"(r) : "l"(a), "l"(b), "l"(c)); return r;
}

// order-preserving float->uint key (handles negatives)
__device__ __forceinline__ unsigned fkey(float f) {
    unsigned b = __float_as_uint(f);
    return b ^ ((b >> 31) ? 0xFFFFFFFFu : 0x80000000u);
}

// ---------------- masked accumulation helper ----------------
template<int MODE>
__device__ __forceinline__ void accum_masked(const void* __restrict__ mask, long mbase,
    const float* __restrict__ pb, float nx, float ny, float nz, float dq,
    int tid, float* acc, float* cnt)
{
    for (int n = tid; n < N_; n += 256) {
        float px = pb[n*3+0], py = pb[n*3+1], pz = pb[n*3+2];
        float pp = fabsf(px*nx + py*ny + pz*nz - dq);
        #pragma unroll
        for (int p = 0; p < P_; p++) {
            long idx = mbase + (long)p * N_ + n;
            bool m;
            if (MODE == 0)      m = ((const unsigned char*)mask)[idx] != 0;
            else if (MODE == 1) m = ((const float*)mask)[idx] != 0.f;
            else                m = ((const int*)mask)[idx] != 0;
            acc[p] += m ? pp : 0.f;
            cnt[p] += m ? 1.f : 0.f;
        }
    }
}

// ---------------- chamfer block: 64 src points, packed-pair targets ----------------
__device__ __forceinline__ void chamfer_block(
    const float* __restrict__ srcBase, const float* __restrict__ tgtBase,
    int nTgt, int accL1, int accL2)
{
    int t = threadIdx.x;
    int pi = t & 63, s = t >> 6;
    float px = srcBase[pi*3+0], py = srcBase[pi*3+1], pz = srcBase[pi*3+2];
    ull npx2 = pack2(-px, -px), npy2 = pack2(-py, -py), npz2 = pack2(-pz, -pz);
    float m1a = 1e30f, m1b = 1e30f, m2a = 1e30f, m2b = 1e30f;
    __shared__ ull ssx[128], ssy[128], ssz[128];
    for (int base = 0; base < nTgt; base += 256) {
        ((float*)ssx)[t] = tgtBase[(base+t)*3+0];
        ((float*)ssy)[t] = tgtBase[(base+t)*3+1];
        ((float*)ssz)[t] = tgtBase[(base+t)*3+2];
        __syncthreads();
        int j0 = s * 32;                   // 32 packed pairs = 64 targets per slice
        #pragma unroll 8
        for (int j = j0; j < j0 + 32; j++) {
            ull dx2 = addx2(ssx[j], npx2); // (tx - px) pairwise; sign irrelevant
            ull dy2 = addx2(ssy[j], npy2);
            ull dz2 = addx2(ssz[j], npz2);
            ull s2  = fmax2(dx2, dx2, fmax2(dy2, dy2, mulx2(dz2, dz2)));
            float l2l, l2h; unpack2(s2, l2l, l2h);
            m2a = fminf(m2a, l2l); m2b = fminf(m2b, l2h);
            float dxl, dxh, dyl, dyh, dzl, dzh;
            unpack2(dx2, dxl, dxh); unpack2(dy2, dyl, dyh); unpack2(dz2, dzl, dzh);
            float l1l = fabsf(dxl) + fabsf(dyl) + fabsf(dzl);   // abs folds into FADD
            float l1h = fabsf(dxh) + fabsf(dyh) + fabsf(dzh);
            m1a = fminf(m1a, l1l); m1b = fminf(m1b, l1h);
        }
        __syncthreads();
    }
    float m1 = fminf(m1a, m1b), m2 = fminf(m2a, m2b);
    __shared__ float r1[256], r2[256];
    r1[t] = m1; r2[t] = m2;
    __syncthreads();
    if (t < 64) {
        float a1 = fminf(fminf(r1[t], r1[t+64]), fminf(r1[t+128], r1[t+192]));
        float a2 = fminf(fminf(r2[t], r2[t+64]), fminf(r2[t+128], r2[t+192]));
        #pragma unroll
        for (int off = 16; off; off >>= 1) {
            a1 += __shfl_down_sync(0xffffffffu, a1, off);
            a2 += __shfl_down_sync(0xffffffffu, a2, off);
        }
        if ((t & 31) == 0) { r1[t] = a1; r2[t] = a2; }
    }
    __syncthreads();
    if (t == 0) {
        atomicAdd(&g_accs[accL1], r1[0] + r1[32]);
        atomicAdd(&g_accs[accL2], r2[0] + r2[32]);
    }
}

// ---------------- kernel 1: cost matrix + chamfer + repulsion (fused grid) ----------------
__global__ void __launch_bounds__(256) k1(const float* __restrict__ points,
                       const float* __restrict__ pn, const float* __restrict__ pd,
                       const float* __restrict__ gn, const float* __restrict__ gd,
                       const void* __restrict__ mask,
                       const float* __restrict__ rec, const float* __restrict__ gt)
{
    int bid = blockIdx.x;
    int t = threadIdx.x;

    if (bid < COST_BLOCKS) {
        int b = bid / Q_, q = bid % Q_;

        // mask dtype detection: block-parallel scan of first 8KB
        const unsigned char* mraw = (const unsigned char*)mask;
        bool big = false, odd = false;
        #pragma unroll 4
        for (int i = t*32; i < t*32 + 32; i++) {
            unsigned char vch = mraw[i];
            big |= (vch > 1);
            odd |= (vch == 1) && ((i & 3) != 0);
        }
        int anyBig = __syncthreads_or(big ? 1 : 0);
        int anyOdd = __syncthreads_or(odd ? 1 : 0);
        int mode = anyBig ? 1 : (anyOdd ? 0 : 2);

        float nx = pn[(b*Q_ + q)*3 + 0];
        float ny = pn[(b*Q_ + q)*3 + 1];
        float nz = pn[(b*Q_ + q)*3 + 2];
        float dq = pd[b*Q_ + q];

        __shared__ float s_acc[P_], s_cnt[P_];
        if (t < P_) { s_acc[t] = 0.f; s_cnt[t] = 0.f; }
        __syncthreads();

        float acc[P_], cnt[P_];
        #pragma unroll
        for (int p = 0; p < P_; p++) { acc[p] = 0.f; cnt[p] = 0.f; }

        const float* pb = points + (size_t)b * N_ * 3;
        const long mbase = (long)b * P_ * N_;
        if (mode == 1)      accum_masked<1>(mask, mbase, pb, nx, ny, nz, dq, t, acc, cnt);
        else if (mode == 0) accum_masked<0>(mask, mbase, pb, nx, ny, nz, dq, t, acc, cnt);
        else                accum_masked<2>(mask, mbase, pb, nx, ny, nz, dq, t, acc, cnt);

        #pragma unroll
        for (int p = 0; p < P_; p++) {
            float v = acc[p], c = cnt[p];
            #pragma unroll
            for (int off = 16; off; off >>= 1) {
                v += __shfl_down_sync(0xffffffffu, v, off);
                c += __shfl_down_sync(0xffffffffu, c, off);
            }
            if ((t & 31) == 0) { atomicAdd(&s_acc[p], v); atomicAdd(&s_cnt[p], c); }
        }
        __syncthreads();

        if (t < P_) {
            int p = t;
            float c = s_cnt[p];
            float cham = s_acc[p] / fmaxf(c, 1.f);
            float ns = 1.f - fabsf(nx*gn[(b*P_+p)*3+0] + ny*gn[(b*P_+p)*3+1] + nz*gn[(b*P_+p)*3+2]);
            float dd = fabsf(dq - gd[b*P_ + p]);
            int has = c > 0.f;
            g_cham [b][q][p] = cham;
            g_nsim [b][q][p] = ns;
            g_ddiff[b][q][p] = dd;
            g_costT[b][p][q] = ns + 0.5f*dd + 5.f*(has ? cham : 1.f);
            if (q == 0) g_cnt[b][p] = c;
        }
    } else if (bid < COST_BLOCKS + CH1_BLOCKS) {
        int id = bid - COST_BLOCKS;
        int b  = id / (M_/64);
        int mc = id % (M_/64);
        chamfer_block(rec + ((size_t)b*M_ + mc*64)*3, gt + (size_t)b*G_*3, G_, 1, 2);
    } else if (bid < COST_BLOCKS + CH1_BLOCKS + CH2_BLOCKS) {
        int id = bid - COST_BLOCKS - CH1_BLOCKS;
        int b  = id / (G_/64);
        int gc = id % (G_/64);
        chamfer_block(gt + ((size_t)b*G_ + gc*64)*3, rec + (size_t)b*M_*3, M_, 3, 4);
    } else {
        // repulsion: 4 (b,q) groups per block
        int id = bid - COST_BLOCKS - CH1_BLOCKS - CH2_BLOCKS;   // 0..39
        int sub = t >> 6;
        int i = t & 63;
        int gq = id*4 + sub;
        int b = gq / Q_, q = gq % Q_;
        __shared__ float sx[4][FAC_], sy[4][FAC_], sz[4][FAC_];
        const float* base = rec + ((size_t)b*M_ + q*FAC_)*3;
        sx[sub][i] = base[i*3+0]; sy[sub][i] = base[i*3+1]; sz[sub][i] = base[i*3+2];
        __syncthreads();
        float px = sx[sub][i], py = sy[sub][i], pz = sz[sub][i];
        float best[KNN_];
        #pragma unroll
        for (int k = 0; k < KNN_; k++) best[k] = 1e30f;
        for (int j = 0; j < FAC_; j++) {
            if (j == i) continue;
            float dx = px-sx[sub][j], dy = py-sy[sub][j], dz = pz-sz[sub][j];
            float vv = fmaf(dx, dx, fmaf(dy, dy, dz*dz));
            #pragma unroll
            for (int k = 0; k < KNN_; k++) {
                float lo = fminf(best[k], vv);
                vv = fmaxf(best[k], vv);
                best[k] = lo;
            }
        }
        float s = 0.f;
        #pragma unroll
        for (int k = 0; k < KNN_; k++) {
            float dn = fmaxf(best[k], REP_EPS);
            s += (RADIUS_ - sqrtf(dn)) * expf(-dn / BW2);
        }
        #pragma unroll
        for (int off = 16; off; off >>= 1) s += __shfl_down_sync(0xffffffffu, s, off);
        __shared__ float sw[8];
        if ((t & 31) == 0) sw[t >> 5] = s;
        __syncthreads();
        if (i == 0) {
            float tot = sw[sub*2] + sw[sub*2 + 1];
            atomicAdd(&g_accs[0], fmaxf(tot / (float)(FAC_*KNN_), 0.f));
        }
    }
}

// ---------------- kernel 2: greedy-init JV Hungarian + cls + final combine ----------------
__global__ void __launch_bounds__(256) k2(const float* __restrict__ logits,
                                          float* __restrict__ out)
{
    __shared__ float cost_s[B_][P_*Q_];
    __shared__ float u_s[B_][P_ + 1];
    __shared__ float red[3][256];
    int t = threadIdx.x;
    int w = t >> 5;        // warp = batch
    int lane = t & 31;
    const unsigned FULL = 0xffffffffu;

    const float* csrc = &g_costT[0][0][0];
    for (int idx = t; idx < B_*P_*Q_; idx += 256)
        (&cost_s[0][0])[idx] = csrc[idx];
    __syncthreads();
    if (lane == 0) u_s[w][0] = 0.f;

    // ---- greedy row-reduction init ----
    float v = 0.f;
    int p = 0;                                       // lane j: row assigned to col j (0 = free)
    unsigned free_mask = ((1u << Q_) - 1u) << 1;     // cols 1..Q_ free
    unsigned todo = 0;
    for (int i = 1; i <= P_; i++) {
        float c = (lane >= 1 && lane <= Q_) ? cost_s[w][(i-1)*Q_ + (lane-1)] : 1e30f;
        unsigned key = (lane >= 1 && lane <= Q_) ? ((fkey(c) & ~31u) | (unsigned)lane)
                                                 : 0xFFFFFFFFu;
        key = __reduce_min_sync(FULL, key);
        int jm = (int)(key & 31u);
        float ui = __shfl_sync(FULL, c, jm);
        if (lane == 0) u_s[w][i] = ui;
        if ((free_mask >> jm) & 1u) {
            if (lane == jm) p = i;
            free_mask &= ~(1u << jm);
        } else {
            todo |= (1u << i);
        }
    }
    __syncwarp();

    // ---- augment remaining rows ----
    float minv = 0.f;
    int way = 0, used = 0;
    for (int i = 1; i <= P_; i++) {
        if (!((todo >> i) & 1u)) continue;
        if (lane == 0) p = i;
        minv = 1e30f; used = 0;
        int j0 = 0;
        while (true) {
            if (lane == j0) used = 1;
            int i0 = __shfl_sync(FULL, p, j0);
            float u0 = u_s[w][i0];
            bool active = (lane >= 1) && (lane <= Q_) && !used;
            if (active) {
                float cur = cost_s[w][(i0-1)*Q_ + (lane-1)] - u0 - v;
                if (cur < minv) { minv = cur; way = j0; }
            }
            unsigned key = active ? ((fkey(minv) & ~31u) | (unsigned)lane)
                                  : 0xFFFFFFFFu;
            key = __reduce_min_sync(FULL, key);
            int j1 = (int)(key & 31u);
            float delta = __shfl_sync(FULL, minv, j1);
            if (lane <= Q_) {
                if (used)           { u_s[w][p] += delta; v -= delta; }
                else if (lane >= 1) { minv -= delta; }
            }
            __syncwarp();
            j0 = j1;
            if ((free_mask >> j0) & 1u) break;
        }
        free_mask &= ~(1u << j0);
        while (j0 != 0) {
            int wy = __shfl_sync(FULL, way, j0);
            int pw = __shfl_sync(FULL, p, wy);
            if (lane == j0) p = pw;
            j0 = wy;
        }
    }
    if (lane >= 1 && lane <= Q_ && p >= 1)
        g_rows[w][p - 1] = lane - 1;
    __syncthreads();

    // ---- cls / param / pvd ----
    float c_cls = 0.f, c_par = 0.f, c_pvd = 0.f;
    if (t < B_*Q_) {
        int b = t / Q_, q = t % Q_;
        float tgt = 0.f;
        #pragma unroll
        for (int pp = 0; pp < P_; pp++) tgt += (g_rows[b][pp] == q) ? 1.f : 0.f;
        float x = logits[t];
        c_cls = fmaxf(x, 0.f) - x*tgt + log1pf(expf(-fabsf(x)));
    }
    if (t < B_*P_) {
        int b = t / P_, pp = t % P_;
        int r = g_rows[b][pp];
        c_par = g_nsim[b][r][pp] + g_ddiff[b][r][pp];
        c_pvd = (g_cnt[b][pp] > 0.f) ? g_cham[b][r][pp] : 0.f;
    }
    red[0][t] = c_cls; red[1][t] = c_par; red[2][t] = c_pvd;
    __syncthreads();
    for (int off = 128; off; off >>= 1) {
        if (t < off) {
            red[0][t] += red[0][t+off]; red[1][t] += red[1][t+off]; red[2][t] += red[2][t+off];
        }
        __syncthreads();
    }
    if (t == 0) {
        float ch1 = 0.5f * (g_accs[1] / (float)BM + g_accs[3] / (float)BG);
        float ch2 = 0.5f * (g_accs[2] / (float)BM + g_accs[4] / (float)BG);
        out[0] = red[0][0] / (float)(B_*Q_)
               + 0.5f  * red[1][0] / (float)(B_*P_)
               + 20.f  * red[2][0] / (float)(B_*P_)
               + g_accs[0] / (float)(B_*Q_)
               + ch1 + ch2;
    }
    if (t < 8) g_accs[t] = 0.f;   // restore for next graph replay
}

// ---------------- host launcher ----------------
extern "C" void kernel_launch(void* const* d_in, const int* in_sizes, int n_in,
                              void* d_out, int out_size) {
    const float* pred_logits = nullptr;
    const float* pred_normals = nullptr;
    const float* pred_distances = nullptr;
    const float* gt_normals = nullptr;
    const float* gt_distances = nullptr;
    const void*  gt_masks = nullptr;
    const float* points = nullptr;
    const float* rec = nullptr;
    const float* gt = nullptr;
    int seen160 = 0;
    for (int i = 0; i < n_in; i++) {
        switch (in_sizes[i]) {
            case B_ * Q_:
                if (seen160++ == 0) pred_logits = (const float*)d_in[i];
                else pred_distances = (const float*)d_in[i];
                break;
            case B_ * Q_ * 3: pred_normals = (const float*)d_in[i]; break;
            case B_ * P_ * 3: gt_normals = (const float*)d_in[i]; break;
            case B_ * P_: gt_distances = (const float*)d_in[i]; break;
            case B_ * P_ * N_: gt_masks = d_in[i]; break;
            case B_ * N_ * 3: points = (const float*)d_in[i]; break;
            case B_ * M_ * 3: rec = (const float*)d_in[i]; break;
            case B_ * G_ * 3: gt = (const float*)d_in[i]; break;
            default: break;  // gt_index unused
        }
    }

    k1<<<K1_BLOCKS, 256>>>(points, pred_normals, pred_distances,
                           gt_normals, gt_distances, gt_masks, rec, gt);
    k2<<<1, 256>>>(pred_logits, (float*)d_out);
}